// round 1
// baseline (speedup 1.0000x reference)
#include <cuda_runtime.h>

#define SZ 512
#define BW 128   // band width (columns per warp territory) and rows per warp

__device__ __forceinline__ float wreduce(float s) {
#pragma unroll
    for (int o = 16; o; o >>= 1) s += __shfl_xor_sync(0xffffffffu, s, o);
    return s;
}

__global__ __launch_bounds__(512, 2)
void corner_shells_kernel(const float* __restrict__ x, float* __restrict__ out) {
    // per-plane reduction state
    __shared__ float sBandRow[4][SZ];   // per-column-band row sums
    __shared__ float sColPart[4][SZ];   // per-row-band column sums
    __shared__ float sCutM[SZ];         // Sum_{c in band(jm), c<=r} x[r][c]
    __shared__ float sCutA[SZ];         // Sum_{c in band(ja), c<=511-r} x[r][c]
    __shared__ float sSnapM[SZ];        // warp-local strict col prefix at row==c   (indexed by column c)
    __shared__ float sSnapA[SZ];        // warp-local strict col prefix at row==511-c (indexed by column c)
    __shared__ float sDM[SZ];           // x[r][r]
    __shared__ float sDA[SZ];           // x[r][511-r]
    __shared__ float sRT[SZ], sPM[SZ], sPA[SZ], sA1[SZ], sA2[SZ], sCT[SZ];

    const int p = blockIdx.x;                       // plane = b*8 + ch
    const float* __restrict__ X = x + (size_t)p * SZ * SZ;

    const int tid  = threadIdx.x;
    const int w    = tid >> 5;
    const int lane = tid & 31;
    const int wr = w >> 2, wc = w & 3;              // 4x4 warp grid
    const int r0 = wr * BW, c0 = wc * BW;
    const bool isDiag = (wr == wc);
    const bool isAnti = (wr + wc == 3);

    const float4* __restrict__ base =
        reinterpret_cast<const float4*>(X + (size_t)r0 * SZ + c0) + lane;
    // row stride in float4 units:
    const int RS4 = SZ / 4; // 128

    float4 acc = make_float4(0.f, 0.f, 0.f, 0.f);

    for (int rr = 0; rr < BW; rr += 4) {
        float4 v[4];
#pragma unroll
        for (int u = 0; u < 4; u++)
            v[u] = base[(rr + u) * RS4];

#pragma unroll
        for (int u = 0; u < 4; u++) {
            const int   gr = r0 + rr + u;
            const float4 vv = v[u];
            const float pre1 = vv.x + vv.y;
            const float pre2 = pre1 + vv.z;
            const float s4   = pre2 + vv.w;

            // full band row sum
            float rs = wreduce(s4);
            if (lane == 0) sBandRow[wc][gr] = rs;

            if (isDiag) {
                // main-diagonal cut for row gr: column gr lives in this band (r0==c0)
                const int lc = gr - c0;            // local column of cut, 0..127
                const int ls = lc >> 2, k = lc & 3;
                const float pk = (k == 0) ? vv.x : (k == 1) ? pre1 : (k == 2) ? pre2 : s4;
                float mv = (lane < ls) ? s4 : (lane == ls) ? pk : 0.f;
                mv = wreduce(mv);
                if (lane == 0) sCutM[gr] = mv;
                if (lane == ls) {
                    const float e  = (k==0)?vv.x:(k==1)?vv.y:(k==2)?vv.z:vv.w;
                    const float sn = (k==0)?acc.x:(k==1)?acc.y:(k==2)?acc.z:acc.w;
                    sDM[gr]    = e;    // x[gr][gr]
                    sSnapM[gr] = sn;   // strict warp-local prefix of column gr at row gr
                }
            }
            if (isAnti) {
                // anti-diagonal cut for row gr: column 511-gr lives in this band
                const int gc = SZ - 1 - gr;
                const int lc = gc - c0;
                const int ls = lc >> 2, k = lc & 3;
                const float pk = (k == 0) ? vv.x : (k == 1) ? pre1 : (k == 2) ? pre2 : s4;
                float mv = (lane < ls) ? s4 : (lane == ls) ? pk : 0.f;
                mv = wreduce(mv);
                if (lane == 0) sCutA[gr] = mv;
                if (lane == ls) {
                    const float e  = (k==0)?vv.x:(k==1)?vv.y:(k==2)?vv.z:vv.w;
                    const float sn = (k==0)?acc.x:(k==1)?acc.y:(k==2)?acc.z:acc.w;
                    sDA[gr]    = e;    // x[gr][511-gr]
                    sSnapA[gc] = sn;   // strict warp-local prefix of column gc at row gr==511-gc
                }
            }

            acc.x += vv.x; acc.y += vv.y; acc.z += vv.z; acc.w += vv.w;
        }
    }

    // write per-warp column partials (lane's 4 consecutive columns)
    reinterpret_cast<float4*>(&sColPart[wr][c0])[lane] = acc;
    __syncthreads();

    // ---- per-index combine, step 1: full prefixes ----
    {
        const int i = tid;                       // 0..511
        const float b0 = sBandRow[0][i], b1 = sBandRow[1][i],
                    b2 = sBandRow[2][i], b3 = sBandRow[3][i];
        const float RT = (b0 + b1) + (b2 + b3);

        const int jm = i >> 7;                   // band holding column i / row i
        float PM = sCutM[i];
        if (jm > 0) PM += b0;
        if (jm > 1) PM += b1;
        if (jm > 2) PM += b2;

        const int ja = (SZ - 1 - i) >> 7;        // band holding column 511-i / row 511-i
        float PA = sCutA[i];
        if (ja > 0) PA += b0;
        if (ja > 1) PA += b1;
        if (ja > 2) PA += b2;

        const float q0 = sColPart[0][i], q1 = sColPart[1][i],
                    q2 = sColPart[2][i], q3 = sColPart[3][i];
        const float CT = (q0 + q1) + (q2 + q3);

        float A1 = sSnapM[i];                    // Sum_{r<i} x[r][i]
        if (jm > 0) A1 += q0;
        if (jm > 1) A1 += q1;
        if (jm > 2) A1 += q2;

        float A2 = sSnapA[i];                    // Sum_{r<511-i} x[r][i]
        if (ja > 0) A2 += q0;
        if (ja > 1) A2 += q1;
        if (ja > 2) A2 += q2;

        sRT[i] = RT; sPM[i] = PM; sPA[i] = PA;
        sA1[i] = A1; sA2[i] = A2; sCT[i] = CT;
    }
    __syncthreads();

    // ---- step 2: assemble shells, scale, write out ----
    {
        const int i = tid;
        const int m = SZ - 1 - i;

        const float tl = sPM[i] + sA1[i];
        const float tr = sRT[i] - sPA[i] + sDA[i] + sA2[m];
        const float bl = sPA[m] + sCT[i] - sA2[i] - sDA[m];
        const float br = sRT[m] - sPM[m] + sCT[m] - sA1[m];

        const float inv = 1.0f / (float)(2 * i + 1);

        const int b  = p >> 3;     // batch
        const int ch = p & 7;      // channel
        float* __restrict__ o = out + ((size_t)(b * SZ + i)) * 32 + ch;
        o[0]  = tl * inv;
        o[8]  = tr * inv;
        o[16] = bl * inv;
        o[24] = br * inv;
    }
}

extern "C" void kernel_launch(void* const* d_in, const int* in_sizes, int n_in,
                              void* d_out, int out_size) {
    const float* x = (const float*)d_in[0];
    float* out = (float*)d_out;
    const int planes = in_sizes[0] / (SZ * SZ);   // 32*8 = 256
    corner_shells_kernel<<<planes, 512>>>(x, out);
}

// round 2
// speedup vs baseline: 1.0824x; 1.0824x over previous
#include <cuda_runtime.h>

#define SZ 512
#define BW 128   // band width (columns per warp territory) and rows per warp

// Reduce 4 independent per-lane values over the warp in 6 shuffles.
// Returns: lane L holds the full 32-lane sum of value (L & 3).
__device__ __forceinline__ float multireduce4(float v0, float v1, float v2, float v3, int lane) {
    const unsigned F = 0xffffffffu;
    const bool b0 = lane & 1;
    float a01 = b0 ? v0 : v1;
    float x01 = (b0 ? v1 : v0) + __shfl_xor_sync(F, a01, 1);
    float a23 = b0 ? v2 : v3;
    float x23 = (b0 ? v3 : v2) + __shfl_xor_sync(F, a23, 1);
    const bool b1 = lane & 2;
    float c = b1 ? x01 : x23;
    float y = (b1 ? x23 : x01) + __shfl_xor_sync(F, c, 2);
    y += __shfl_xor_sync(F, y, 4);
    y += __shfl_xor_sync(F, y, 8);
    y += __shfl_xor_sync(F, y, 16);
    return y;
}

__global__ __launch_bounds__(512, 2)
void corner_shells_kernel(const float* __restrict__ x, float* __restrict__ out) {
    __shared__ float sBandRow[4][SZ];   // per-column-band row sums
    __shared__ float sColPart[4][SZ];   // per-row-band column sums
    __shared__ float sCutM[SZ];         // Sum_{c in band(jm), c<=r} x[r][c]
    __shared__ float sCutA[SZ];         // Sum_{c in band(ja), c<=511-r} x[r][c]
    __shared__ float sSnapM[SZ];        // warp-local strict col prefix at row==c
    __shared__ float sSnapA[SZ];        // warp-local strict col prefix at row==511-c
    __shared__ float sDM[SZ];           // x[r][r]
    __shared__ float sDA[SZ];           // x[r][511-r]
    __shared__ float sRT[SZ], sPM[SZ], sPA[SZ], sA1[SZ], sA2[SZ], sCT[SZ];

    const int p = blockIdx.x;
    const float* __restrict__ X = x + (size_t)p * SZ * SZ;

    const int tid  = threadIdx.x;
    const int w    = tid >> 5;
    const int lane = tid & 31;
    const int wr = w >> 2, wc = w & 3;
    const int r0 = wr * BW, c0 = wc * BW;
    const bool isDiag = (wr == wc);
    const bool isAnti = (wr + wc == 3);

    const float4* __restrict__ base =
        reinterpret_cast<const float4*>(X + (size_t)r0 * SZ + c0) + lane;
    const int RS4 = SZ / 4; // 128 float4 per row

    float4 acc = make_float4(0.f, 0.f, 0.f, 0.f);

    // -------- software-pipelined main loop: 32 groups of 4 rows --------
    float4 v0 = __ldcs(base + 0 * RS4);
    float4 v1 = __ldcs(base + 1 * RS4);
    float4 v2 = __ldcs(base + 2 * RS4);
    float4 v3 = __ldcs(base + 3 * RS4);

    for (int g = 0; g < BW / 4; ++g) {
        // prefetch next group (last iteration reloads group 31 harmlessly; L2 hit)
        const int gn = (g < BW / 4 - 1) ? g + 1 : g;
        float4 n0 = __ldcs(base + (4 * gn + 0) * RS4);
        float4 n1 = __ldcs(base + (4 * gn + 1) * RS4);
        float4 n2 = __ldcs(base + (4 * gn + 2) * RS4);
        float4 n3 = __ldcs(base + (4 * gn + 3) * RS4);

        const int gr0 = r0 + 4 * g;

        // per-row lane partial sums
        const float s0 = (v0.x + v0.y) + (v0.z + v0.w);
        const float s1 = (v1.x + v1.y) + (v1.z + v1.w);
        const float s2 = (v2.x + v2.y) + (v2.z + v2.w);
        const float s3 = (v3.x + v3.y) + (v3.z + v3.w);

        // batched reduce: lanes 0..3 hold full row sums for rows gr0..gr0+3
        const float rsum = multireduce4(s0, s1, s2, s3, lane);
        if (lane < 4) sBandRow[wc][gr0 + lane] = rsum;

        if (isDiag) {
            // masked values for the 4 main-diagonal cuts, then one batched reduce
            float m[4];
            const float4 vv[4] = {v0, v1, v2, v3};
            const float  ss[4] = {s0, s1, s2, s3};
#pragma unroll
            for (int u = 0; u < 4; u++) {
                const int gr = gr0 + u;
                const int lc = gr - c0;
                const int ls = lc >> 2, k = lc & 3;
                const float p1 = vv[u].x + vv[u].y;
                const float p2 = p1 + vv[u].z;
                const float pk = (k == 0) ? vv[u].x : (k == 1) ? p1 : (k == 2) ? p2 : ss[u];
                m[u] = (lane < ls) ? ss[u] : (lane == ls) ? pk : 0.f;
            }
            const float mc = multireduce4(m[0], m[1], m[2], m[3], lane);
            if (lane < 4) sCutM[gr0 + lane] = mc;
        }
        if (isAnti) {
            float m[4];
            const float4 vv[4] = {v0, v1, v2, v3};
            const float  ss[4] = {s0, s1, s2, s3};
#pragma unroll
            for (int u = 0; u < 4; u++) {
                const int gr = gr0 + u;
                const int gc = SZ - 1 - gr;
                const int lc = gc - c0;
                const int ls = lc >> 2, k = lc & 3;
                const float p1 = vv[u].x + vv[u].y;
                const float p2 = p1 + vv[u].z;
                const float pk = (k == 0) ? vv[u].x : (k == 1) ? p1 : (k == 2) ? p2 : ss[u];
                m[u] = (lane < ls) ? ss[u] : (lane == ls) ? pk : 0.f;
            }
            const float mc = multireduce4(m[0], m[1], m[2], m[3], lane);
            if (lane < 4) sCutA[gr0 + lane] = mc;
        }

        // per-row: snapshots (strict prefix -> before acc update), then acc update
        {
            const float4 vv[4] = {v0, v1, v2, v3};
#pragma unroll
            for (int u = 0; u < 4; u++) {
                const int gr = gr0 + u;
                if (isDiag) {
                    const int lc = gr - c0;
                    const int ls = lc >> 2, k = lc & 3;
                    if (lane == ls) {
                        const float e  = (k==0)?vv[u].x:(k==1)?vv[u].y:(k==2)?vv[u].z:vv[u].w;
                        const float sn = (k==0)?acc.x:(k==1)?acc.y:(k==2)?acc.z:acc.w;
                        sDM[gr]    = e;
                        sSnapM[gr] = sn;
                    }
                }
                if (isAnti) {
                    const int gc = SZ - 1 - gr;
                    const int lc = gc - c0;
                    const int ls = lc >> 2, k = lc & 3;
                    if (lane == ls) {
                        const float e  = (k==0)?vv[u].x:(k==1)?vv[u].y:(k==2)?vv[u].z:vv[u].w;
                        const float sn = (k==0)?acc.x:(k==1)?acc.y:(k==2)?acc.z:acc.w;
                        sDA[gr]    = e;
                        sSnapA[gc] = sn;
                    }
                }
                acc.x += vv[u].x; acc.y += vv[u].y; acc.z += vv[u].z; acc.w += vv[u].w;
            }
        }

        v0 = n0; v1 = n1; v2 = n2; v3 = n3;
    }

    // per-warp column partials (lane's 4 consecutive columns)
    reinterpret_cast<float4*>(&sColPart[wr][c0])[lane] = acc;
    __syncthreads();

    // ---- per-index combine, step 1: full prefixes ----
    {
        const int i = tid;
        const float b0 = sBandRow[0][i], b1 = sBandRow[1][i],
                    b2 = sBandRow[2][i], b3 = sBandRow[3][i];
        const float RT = (b0 + b1) + (b2 + b3);

        const int jm = i >> 7;
        float PM = sCutM[i];
        if (jm > 0) PM += b0;
        if (jm > 1) PM += b1;
        if (jm > 2) PM += b2;

        const int ja = (SZ - 1 - i) >> 7;
        float PA = sCutA[i];
        if (ja > 0) PA += b0;
        if (ja > 1) PA += b1;
        if (ja > 2) PA += b2;

        const float q0 = sColPart[0][i], q1 = sColPart[1][i],
                    q2 = sColPart[2][i], q3 = sColPart[3][i];
        const float CT = (q0 + q1) + (q2 + q3);

        float A1 = sSnapM[i];
        if (jm > 0) A1 += q0;
        if (jm > 1) A1 += q1;
        if (jm > 2) A1 += q2;

        float A2 = sSnapA[i];
        if (ja > 0) A2 += q0;
        if (ja > 1) A2 += q1;
        if (ja > 2) A2 += q2;

        sRT[i] = RT; sPM[i] = PM; sPA[i] = PA;
        sA1[i] = A1; sA2[i] = A2; sCT[i] = CT;
    }
    __syncthreads();

    // ---- step 2: assemble shells, scale, write out ----
    {
        const int i = tid;
        const int m = SZ - 1 - i;

        const float tl = sPM[i] + sA1[i];
        const float tr = sRT[i] - sPA[i] + sDA[i] + sA2[m];
        const float bl = sPA[m] + sCT[i] - sA2[i] - sDA[m];
        const float br = sRT[m] - sPM[m] + sCT[m] - sA1[m];

        const float inv = 1.0f / (float)(2 * i + 1);

        const int b  = p >> 3;
        const int ch = p & 7;
        float* __restrict__ o = out + ((size_t)(b * SZ + i)) * 32 + ch;
        o[0]  = tl * inv;
        o[8]  = tr * inv;
        o[16] = bl * inv;
        o[24] = br * inv;
    }
}

extern "C" void kernel_launch(void* const* d_in, const int* in_sizes, int n_in,
                              void* d_out, int out_size) {
    const float* x = (const float*)d_in[0];
    float* out = (float*)d_out;
    const int planes = in_sizes[0] / (SZ * SZ);   // 256
    corner_shells_kernel<<<planes, 512>>>(x, out);
}

// round 3
// speedup vs baseline: 1.2371x; 1.1429x over previous
#include <cuda_runtime.h>

#define SZ 512
#define SLAB 128            // rows per slab-block
#define NPLANES 256

// cross-kernel scratch (allocation-free: __device__ globals)
__device__ float g_colsum[NPLANES][4][SZ];  // per-slab column sums
__device__ float g_snapM[NPLANES][SZ];      // strict col prefix within owning slab at row==c
__device__ float g_snapA[NPLANES][SZ];      // strict col prefix within owning slab at row==511-c
__device__ float g_RT[NPLANES][SZ];
__device__ float g_PM[NPLANES][SZ];
__device__ float g_PA[NPLANES][SZ];
__device__ float g_DA[NPLANES][SZ];

// Reduce 4 independent per-lane values over the warp in 6 shuffles.
// Lane L ends holding the full 32-lane sum of value (L & 3).
__device__ __forceinline__ float multireduce4(float v0, float v1, float v2, float v3, int lane) {
    const unsigned F = 0xffffffffu;
    const bool b0 = lane & 1;
    float a01 = b0 ? v0 : v1;
    float x01 = (b0 ? v1 : v0) + __shfl_xor_sync(F, a01, 1);
    float a23 = b0 ? v2 : v3;
    float x23 = (b0 ? v3 : v2) + __shfl_xor_sync(F, a23, 1);
    const bool b1 = lane & 2;
    float c = b1 ? x01 : x23;
    float y = (b1 ? x23 : x01) + __shfl_xor_sync(F, c, 2);
    y += __shfl_xor_sync(F, y, 4);
    y += __shfl_xor_sync(F, y, 8);
    y += __shfl_xor_sync(F, y, 16);
    return y;
}

__global__ __launch_bounds__(512, 2)
void slab_kernel(const float* __restrict__ x) {
    __shared__ float sBandRow[4][SLAB];   // per-col-band row sums (local rows)
    __shared__ float sColPart[4][SZ];     // per-rowgroup column partials
    __shared__ float sCutM[SLAB];         // row prefix (inclusive) at main cut, band part
    __shared__ float sCutA[SLAB];         // row prefix (inclusive) at anti cut, band part
    __shared__ float sSnapM[SLAB];        // warp-local strict col prefix, idx = lr
    __shared__ float sSnapA[SLAB];        // warp-local strict col prefix, idx = 127-lr
    __shared__ float sDA[SLAB];           // x[gr][511-gr], idx = lr

    const int blk = blockIdx.x;
    const int p = blk >> 2;                    // plane
    const int s = blk & 3;                     // slab (row band)
    const float* __restrict__ X = x + ((size_t)p * SZ + (size_t)s * SLAB) * SZ;

    const int tid  = threadIdx.x;
    const int w    = tid >> 5;
    const int lane = tid & 31;
    const int wr = w >> 2, wc = w & 3;         // 4 rowgroups x 4 col bands
    const int c0  = wc * 128;
    const int lr0 = wr * 32;
    const bool mainRole = (wc == s);           // main-diag cuts fall in band s
    const bool antiRole = (wc == 3 - s);       // anti-diag cuts fall in band 3-s

    const float4* __restrict__ base =
        reinterpret_cast<const float4*>(X + (size_t)lr0 * SZ + c0) + lane;
    const int RS4 = SZ / 4;

    float4 acc = make_float4(0.f, 0.f, 0.f, 0.f);

    float4 v0 = __ldcs(base + 0 * RS4);
    float4 v1 = __ldcs(base + 1 * RS4);
    float4 v2 = __ldcs(base + 2 * RS4);
    float4 v3 = __ldcs(base + 3 * RS4);

    for (int g = 0; g < 8; ++g) {
        const int gn = (g < 7) ? g + 1 : g;
        float4 n0 = __ldcs(base + (4 * gn + 0) * RS4);
        float4 n1 = __ldcs(base + (4 * gn + 1) * RS4);
        float4 n2 = __ldcs(base + (4 * gn + 2) * RS4);
        float4 n3 = __ldcs(base + (4 * gn + 3) * RS4);

        const int lrg = lr0 + 4 * g;           // first local row of this group

        const float s0 = (v0.x + v0.y) + (v0.z + v0.w);
        const float s1 = (v1.x + v1.y) + (v1.z + v1.w);
        const float s2 = (v2.x + v2.y) + (v2.z + v2.w);
        const float s3 = (v3.x + v3.y) + (v3.z + v3.w);

        const float rsum = multireduce4(s0, s1, s2, s3, lane);
        if (lane < 4) sBandRow[wc][lrg + lane] = rsum;

        if (mainRole | antiRole) {
            const float4 vv[4] = {v0, v1, v2, v3};
            const float  ssv[4] = {s0, s1, s2, s3};
            float mm[4];
#pragma unroll
            for (int u = 0; u < 4; u++) {
                const int lr = lrg + u;
                const int lc = mainRole ? lr : (127 - lr);
                const int ls = lc >> 2, k = lc & 3;
                const float p1 = vv[u].x + vv[u].y;
                const float p2 = p1 + vv[u].z;
                const float pk = (k == 0) ? vv[u].x : (k == 1) ? p1 : (k == 2) ? p2 : ssv[u];
                mm[u] = (lane < ls) ? ssv[u] : (lane == ls) ? pk : 0.f;
            }
            const float mc = multireduce4(mm[0], mm[1], mm[2], mm[3], lane);
            if (lane < 4) {
                if (mainRole) sCutM[lrg + lane] = mc;
                else          sCutA[lrg + lane] = mc;
            }
        }

        // snapshots (strict prefixes -> before acc update) + acc update
        {
            const float4 vv[4] = {v0, v1, v2, v3};
#pragma unroll
            for (int u = 0; u < 4; u++) {
                const int lr = lrg + u;
                if (mainRole) {
                    const int ls = lr >> 2, k = lr & 3;
                    if (lane == ls) {
                        const float sn = (k==0)?acc.x:(k==1)?acc.y:(k==2)?acc.z:acc.w;
                        sSnapM[lr] = sn;
                    }
                }
                if (antiRole) {
                    const int lc = 127 - lr;
                    const int ls = lc >> 2, k = lc & 3;
                    if (lane == ls) {
                        const float e  = (k==0)?vv[u].x:(k==1)?vv[u].y:(k==2)?vv[u].z:vv[u].w;
                        const float sn = (k==0)?acc.x:(k==1)?acc.y:(k==2)?acc.z:acc.w;
                        sSnapA[lc] = sn;
                        sDA[lr]    = e;
                    }
                }
                acc.x += vv[u].x; acc.y += vv[u].y; acc.z += vv[u].z; acc.w += vv[u].w;
            }
        }

        v0 = n0; v1 = n1; v2 = n2; v3 = n3;
    }

    reinterpret_cast<float4*>(&sColPart[wr][c0])[lane] = acc;
    __syncthreads();

    // ---- slab combine: columns ----
    {
        const int c = tid;
        const float q0 = sColPart[0][c], q1 = sColPart[1][c],
                    q2 = sColPart[2][c], q3 = sColPart[3][c];
        g_colsum[p][s][c] = (q0 + q1) + (q2 + q3);

        const int band = c >> 7;
        if (band == s) {                       // main snapshot owner
            const int lr = c - 128 * s;
            const int rg = lr >> 5;
            float sn = sSnapM[lr];
            if (rg > 0) sn += q0;
            if (rg > 1) sn += q1;
            if (rg > 2) sn += q2;
            g_snapM[p][c] = sn;
        }
        if (band == 3 - s) {                   // anti snapshot owner
            const int la = c - 128 * (3 - s);  // == 127 - lr
            const int rg = (127 - la) >> 5;
            float sn = sSnapA[la];
            if (rg > 0) sn += q0;
            if (rg > 1) sn += q1;
            if (rg > 2) sn += q2;
            g_snapA[p][c] = sn;
        }
    }
    // ---- slab combine: rows ----
    if (tid < SLAB) {
        const int lr = tid;
        const int gr = 128 * s + lr;
        const float b0 = sBandRow[0][lr], b1 = sBandRow[1][lr],
                    b2 = sBandRow[2][lr], b3 = sBandRow[3][lr];
        g_RT[p][gr] = (b0 + b1) + (b2 + b3);

        float pm = sCutM[lr];
        if (s > 0) pm += b0;
        if (s > 1) pm += b1;
        if (s > 2) pm += b2;
        g_PM[p][gr] = pm;

        const int ab = 3 - s;
        float pa = sCutA[lr];
        if (ab > 0) pa += b0;
        if (ab > 1) pa += b1;
        if (ab > 2) pa += b2;
        g_PA[p][gr] = pa;

        g_DA[p][gr] = sDA[lr];
    }
}

__global__ __launch_bounds__(512)
void combine_kernel(float* __restrict__ out) {
    __shared__ float sA1[SZ], sA2[SZ], sCT[SZ], sRT[SZ], sPM[SZ], sPA[SZ], sDA[SZ];
    const int p = blockIdx.x;
    const int i = threadIdx.x;

    const float c0 = g_colsum[p][0][i], c1 = g_colsum[p][1][i],
                c2 = g_colsum[p][2][i], c3 = g_colsum[p][3][i];
    sCT[i] = (c0 + c1) + (c2 + c3);

    const int jm = i >> 7;
    float a1 = g_snapM[p][i];
    if (jm > 0) a1 += c0;
    if (jm > 1) a1 += c1;
    if (jm > 2) a1 += c2;
    sA1[i] = a1;

    const int ja = (SZ - 1 - i) >> 7;
    float a2 = g_snapA[p][i];
    if (ja > 0) a2 += c0;
    if (ja > 1) a2 += c1;
    if (ja > 2) a2 += c2;
    sA2[i] = a2;

    sRT[i] = g_RT[p][i]; sPM[i] = g_PM[p][i]; sPA[i] = g_PA[p][i]; sDA[i] = g_DA[p][i];
    __syncthreads();

    const int m = SZ - 1 - i;
    const float tl = sPM[i] + sA1[i];
    const float tr = sRT[i] - sPA[i] + sDA[i] + sA2[m];
    const float bl = sPA[m] + sCT[i] - sA2[i] - sDA[m];
    const float br = sRT[m] - sPM[m] + sCT[m] - sA1[m];

    const float inv = 1.0f / (float)(2 * i + 1);
    const int b  = p >> 3;
    const int ch = p & 7;
    float* __restrict__ o = out + ((size_t)(b * SZ + i)) * 32 + ch;
    o[0]  = tl * inv;
    o[8]  = tr * inv;
    o[16] = bl * inv;
    o[24] = br * inv;
}

extern "C" void kernel_launch(void* const* d_in, const int* in_sizes, int n_in,
                              void* d_out, int out_size) {
    const float* x = (const float*)d_in[0];
    float* out = (float*)d_out;
    const int planes = in_sizes[0] / (SZ * SZ);   // 256
    slab_kernel<<<planes * 4, 512>>>(x);
    combine_kernel<<<planes, 512>>>(out);
}

// round 4
// speedup vs baseline: 1.4716x; 1.1895x over previous
#include <cuda_runtime.h>

#define SZ 512
#define SLAB 128
#define NPLANES 256

// cross-block scratch (allocation-free: __device__ globals)
__device__ float g_colsum[NPLANES][4][SZ];
__device__ float g_snapM[NPLANES][SZ];
__device__ float g_snapA[NPLANES][SZ];
__device__ float g_RT[NPLANES][SZ];
__device__ float g_PM[NPLANES][SZ];
__device__ float g_PA[NPLANES][SZ];
__device__ float g_DA[NPLANES][SZ];
__device__ unsigned int g_cnt[NPLANES];   // zero-init at load; reset by last block each launch

// Reduce 8 independent per-lane values over the warp in 9 shuffles.
// Lane L ends holding the full 32-lane sum of value (L & 7).
__device__ __forceinline__ float multireduce8(const float* v, int lane) {
    const unsigned F = 0xffffffffu;
    const bool b0 = lane & 1;
    float x01 = (b0 ? v[1] : v[0]) + __shfl_xor_sync(F, b0 ? v[0] : v[1], 1);
    float x23 = (b0 ? v[3] : v[2]) + __shfl_xor_sync(F, b0 ? v[2] : v[3], 1);
    float x45 = (b0 ? v[5] : v[4]) + __shfl_xor_sync(F, b0 ? v[4] : v[5], 1);
    float x67 = (b0 ? v[7] : v[6]) + __shfl_xor_sync(F, b0 ? v[6] : v[7], 1);
    const bool b1 = lane & 2;
    float y03 = (b1 ? x23 : x01) + __shfl_xor_sync(F, b1 ? x01 : x23, 2);
    float y47 = (b1 ? x67 : x45) + __shfl_xor_sync(F, b1 ? x45 : x67, 2);
    const bool b2 = lane & 4;
    float z = (b2 ? y47 : y03) + __shfl_xor_sync(F, b2 ? y03 : y47, 4);
    z += __shfl_xor_sync(F, z, 8);
    z += __shfl_xor_sync(F, z, 16);
    return z;
}

__global__ __launch_bounds__(512, 2)
void slab_kernel(const float* __restrict__ x, float* __restrict__ out) {
    __shared__ float sBandRow[4][SLAB];
    __shared__ float sColPart[4][SZ];
    __shared__ float sCutM[SLAB];
    __shared__ float sCutA[SLAB];
    __shared__ float sSnapM[SLAB];
    __shared__ float sSnapA[SLAB];
    __shared__ float sDA[SLAB];
    // combine-phase scratch (used only by the last block of each plane)
    __shared__ float cA1[SZ], cA2[SZ], cCT[SZ], cRT[SZ], cPM[SZ], cPA[SZ], cDAo[SZ];
    __shared__ bool amLast;

    const int blk = blockIdx.x;
    const int p = blk >> 2;                    // plane
    const int s = blk & 3;                     // slab (row band)
    const float* __restrict__ X = x + ((size_t)p * SZ + (size_t)s * SLAB) * SZ;

    const int tid  = threadIdx.x;
    const int w    = tid >> 5;
    const int lane = tid & 31;
    const int wr = w >> 2, wc = w & 3;         // 4 rowgroups x 4 col bands
    const int c0  = wc * 128;
    const int lr0 = wr * 32;
    const bool mainRole = (wc == s);
    const bool antiRole = (wc == 3 - s);

    const float4* __restrict__ base =
        reinterpret_cast<const float4*>(X + (size_t)lr0 * SZ + c0) + lane;
    const int RS4 = SZ / 4;

    float4 acc = make_float4(0.f, 0.f, 0.f, 0.f);

#pragma unroll
    for (int g = 0; g < 4; ++g) {
        const int lrg = lr0 + 8 * g;

        float4 v[8];
#pragma unroll
        for (int u = 0; u < 8; u++)
            v[u] = __ldcs(base + (8 * g + u) * RS4);

        float sv[8];
#pragma unroll
        for (int u = 0; u < 8; u++)
            sv[u] = (v[u].x + v[u].y) + (v[u].z + v[u].w);

        const float r8 = multireduce8(sv, lane);
        if (lane < 8) sBandRow[wc][lrg + lane] = r8;

        if (mainRole | antiRole) {
            float m[8];
#pragma unroll
            for (int u = 0; u < 8; u++) {
                const int lr = lrg + u;
                const int lc = mainRole ? lr : (127 - lr);
                const int ls = lc >> 2, k = lc & 3;
                const float p1 = v[u].x + v[u].y;
                const float p2 = p1 + v[u].z;
                const float pk = (k == 0) ? v[u].x : (k == 1) ? p1 : (k == 2) ? p2 : sv[u];
                m[u] = (lane < ls) ? sv[u] : (lane == ls) ? pk : 0.f;
            }
            const float mc = multireduce8(m, lane);
            if (lane < 8) {
                if (mainRole) sCutM[lrg + lane] = mc;
                else          sCutA[lrg + lane] = mc;
            }
        }

        // snapshots (strict col prefixes -> before acc update) + acc update
#pragma unroll
        for (int u = 0; u < 8; u++) {
            const int lr = lrg + u;
            if (mainRole) {
                const int ls = lr >> 2, k = lr & 3;
                if (lane == ls) {
                    const float sn = (k==0)?acc.x:(k==1)?acc.y:(k==2)?acc.z:acc.w;
                    sSnapM[lr] = sn;
                }
            }
            if (antiRole) {
                const int lc = 127 - lr;
                const int ls = lc >> 2, k = lc & 3;
                if (lane == ls) {
                    const float e  = (k==0)?v[u].x:(k==1)?v[u].y:(k==2)?v[u].z:v[u].w;
                    const float sn = (k==0)?acc.x:(k==1)?acc.y:(k==2)?acc.z:acc.w;
                    sSnapA[lc] = sn;
                    sDA[lr]    = e;
                }
            }
            acc.x += v[u].x; acc.y += v[u].y; acc.z += v[u].z; acc.w += v[u].w;
        }
    }

    reinterpret_cast<float4*>(&sColPart[wr][c0])[lane] = acc;
    __syncthreads();

    // ---- slab combine: columns ----
    {
        const int c = tid;
        const float q0 = sColPart[0][c], q1 = sColPart[1][c],
                    q2 = sColPart[2][c], q3 = sColPart[3][c];
        g_colsum[p][s][c] = (q0 + q1) + (q2 + q3);

        const int band = c >> 7;
        if (band == s) {
            const int lr = c - 128 * s;
            const int rg = lr >> 5;
            float sn = sSnapM[lr];
            if (rg > 0) sn += q0;
            if (rg > 1) sn += q1;
            if (rg > 2) sn += q2;
            g_snapM[p][c] = sn;
        }
        if (band == 3 - s) {
            const int la = c - 128 * (3 - s);   // == 127 - lr
            const int rg = (127 - la) >> 5;
            float sn = sSnapA[la];
            if (rg > 0) sn += q0;
            if (rg > 1) sn += q1;
            if (rg > 2) sn += q2;
            g_snapA[p][c] = sn;
        }
    }
    // ---- slab combine: rows ----
    if (tid < SLAB) {
        const int lr = tid;
        const int gr = 128 * s + lr;
        const float b0 = sBandRow[0][lr], b1 = sBandRow[1][lr],
                    b2 = sBandRow[2][lr], b3 = sBandRow[3][lr];
        g_RT[p][gr] = (b0 + b1) + (b2 + b3);

        float pm = sCutM[lr];
        if (s > 0) pm += b0;
        if (s > 1) pm += b1;
        if (s > 2) pm += b2;
        g_PM[p][gr] = pm;

        const int ab = 3 - s;
        float pa = sCutA[lr];
        if (ab > 0) pa += b0;
        if (ab > 1) pa += b1;
        if (ab > 2) pa += b2;
        g_PA[p][gr] = pa;

        g_DA[p][gr] = sDA[lr];
    }

    // ---- last-block-per-plane fused combine ----
    __threadfence();
    __syncthreads();
    if (tid == 0) {
        const unsigned t = atomicAdd(&g_cnt[p], 1u);
        amLast = (t == 3u);
        if (amLast) g_cnt[p] = 0;   // self-reset for graph replay determinism
    }
    __syncthreads();
    if (!amLast) return;

    {
        const int i = tid;
        const float q0 = g_colsum[p][0][i], q1 = g_colsum[p][1][i],
                    q2 = g_colsum[p][2][i], q3 = g_colsum[p][3][i];
        cCT[i] = (q0 + q1) + (q2 + q3);

        const int jm = i >> 7;
        float a1 = g_snapM[p][i];
        if (jm > 0) a1 += q0;
        if (jm > 1) a1 += q1;
        if (jm > 2) a1 += q2;
        cA1[i] = a1;

        const int ja = (SZ - 1 - i) >> 7;
        float a2 = g_snapA[p][i];
        if (ja > 0) a2 += q0;
        if (ja > 1) a2 += q1;
        if (ja > 2) a2 += q2;
        cA2[i] = a2;

        cRT[i] = g_RT[p][i]; cPM[i] = g_PM[p][i]; cPA[i] = g_PA[p][i]; cDAo[i] = g_DA[p][i];
    }
    __syncthreads();
    {
        const int i = tid;
        const int m = SZ - 1 - i;

        const float tl = cPM[i] + cA1[i];
        const float tr = cRT[i] - cPA[i] + cDAo[i] + cA2[m];
        const float bl = cPA[m] + cCT[i] - cA2[i] - cDAo[m];
        const float br = cRT[m] - cPM[m] + cCT[m] - cA1[m];

        const float inv = 1.0f / (float)(2 * i + 1);
        const int b  = p >> 3;
        const int ch = p & 7;
        float* __restrict__ o = out + ((size_t)(b * SZ + i)) * 32 + ch;
        o[0]  = tl * inv;
        o[8]  = tr * inv;
        o[16] = bl * inv;
        o[24] = br * inv;
    }
}

extern "C" void kernel_launch(void* const* d_in, const int* in_sizes, int n_in,
                              void* d_out, int out_size) {
    const float* x = (const float*)d_in[0];
    float* out = (float*)d_out;
    const int planes = in_sizes[0] / (SZ * SZ);   // 256
    slab_kernel<<<planes * 4, 512>>>(x, out);
}

// round 5
// speedup vs baseline: 1.6337x; 1.1101x over previous
#include <cuda_runtime.h>
#include <cstdint>

#define SZ 512
#define SLAB 128
#define NPLANES 256

// cross-block scratch (allocation-free: __device__ globals)
__device__ float g_colsum[NPLANES][4][SZ];
__device__ float g_snapM[NPLANES][SZ];
__device__ float g_snapA[NPLANES][SZ];
__device__ float g_RT[NPLANES][SZ];
__device__ float g_PM[NPLANES][SZ];
__device__ float g_PA[NPLANES][SZ];
__device__ float g_DA[NPLANES][SZ];
__device__ unsigned int g_cnt[NPLANES];   // zero-init; self-reset each launch

__device__ __forceinline__ uint64_t pack2(float lo, float hi) {
    uint64_t d;
    asm("mov.b64 %0, {%1, %2};" : "=l"(d) : "f"(lo), "f"(hi));
    return d;
}
__device__ __forceinline__ void unpack2(uint64_t d, float& lo, float& hi) {
    asm("mov.b64 {%0, %1}, %2;" : "=f"(lo), "=f"(hi) : "l"(d));
}
__device__ __forceinline__ uint64_t addf32x2(uint64_t a, uint64_t b) {
    uint64_t d;
    asm("add.rn.f32x2 %0, %1, %2;" : "=l"(d) : "l"(a), "l"(b));
    return d;
}

// Reduce 8 independent per-lane values over the warp in 9 shuffles.
// Lane L ends holding the full 32-lane sum of value (L & 7).
__device__ __forceinline__ float multireduce8(const float* v, int lane) {
    const unsigned F = 0xffffffffu;
    const bool b0 = lane & 1;
    float x01 = (b0 ? v[1] : v[0]) + __shfl_xor_sync(F, b0 ? v[0] : v[1], 1);
    float x23 = (b0 ? v[3] : v[2]) + __shfl_xor_sync(F, b0 ? v[2] : v[3], 1);
    float x45 = (b0 ? v[5] : v[4]) + __shfl_xor_sync(F, b0 ? v[4] : v[5], 1);
    float x67 = (b0 ? v[7] : v[6]) + __shfl_xor_sync(F, b0 ? v[6] : v[7], 1);
    const bool b1 = lane & 2;
    float y03 = (b1 ? x23 : x01) + __shfl_xor_sync(F, b1 ? x01 : x23, 2);
    float y47 = (b1 ? x67 : x45) + __shfl_xor_sync(F, b1 ? x45 : x67, 2);
    const bool b2 = lane & 4;
    float z = (b2 ? y47 : y03) + __shfl_xor_sync(F, b2 ? y03 : y47, 4);
    z += __shfl_xor_sync(F, z, 8);
    z += __shfl_xor_sync(F, z, 16);
    return z;
}

__global__ __launch_bounds__(512, 2)
void slab_kernel(const float* __restrict__ x, float* __restrict__ out) {
    __shared__ float sBandRow[4][SLAB];
    __shared__ float sColPart[4][SZ];
    __shared__ float sCutM[SLAB];
    __shared__ float sCutA[SLAB];
    __shared__ float sSnapM[SLAB];
    __shared__ float sSnapA[SLAB];
    __shared__ float sDA[SLAB];
    __shared__ float cA1[SZ], cA2[SZ], cCT[SZ], cRT[SZ], cPM[SZ], cPA[SZ], cDAo[SZ];
    __shared__ bool amLast;

    const int blk = blockIdx.x;
    const int p = blk >> 2;
    const int s = blk & 3;
    const float* __restrict__ X = x + ((size_t)p * SZ + (size_t)s * SLAB) * SZ;

    const int tid  = threadIdx.x;
    const int w    = tid >> 5;
    const int lane = tid & 31;
    const int wr = w >> 2, wc = w & 3;
    const int c0  = wc * 128;
    const int lr0 = wr * 32;
    const bool mainRole = (wc == s);
    const bool antiRole = (wc == 3 - s);

    const float4* __restrict__ base =
        reinterpret_cast<const float4*>(X + (size_t)lr0 * SZ + c0) + lane;
    const int RS4 = SZ / 4;

    uint64_t acc01 = 0ull, acc23 = 0ull;   // packed (0.f,0.f)

#pragma unroll
    for (int g = 0; g < 4; ++g) {
        const int lrg = lr0 + 8 * g;

        float4 v[8];
#pragma unroll
        for (int u = 0; u < 8; u++)
            v[u] = __ldcs(base + (8 * g + u) * RS4);

        float sv[8];
#pragma unroll
        for (int u = 0; u < 8; u++) {
            uint64_t h = addf32x2(pack2(v[u].x, v[u].y), pack2(v[u].z, v[u].w));
            float lo, hi; unpack2(h, lo, hi);
            sv[u] = lo + hi;
        }

        const float r8 = multireduce8(sv, lane);
        if (lane < 8) sBandRow[wc][lrg + lane] = r8;

        if (mainRole) {
            // cut column for local row lr is lr itself; k = u&3 (compile-time),
            // ls constant per half-group.
            const int ls0 = 8 * wr + 2 * g;
            float m[8];
            {
                const bool lt = lane < ls0, eq = lane == ls0;
                m[0] = lt ? sv[0] : eq ? v[0].x : 0.f;
                m[1] = lt ? sv[1] : eq ? (v[1].x + v[1].y) : 0.f;
                m[2] = lt ? sv[2] : eq ? ((v[2].x + v[2].y) + v[2].z) : 0.f;
                m[3] = (lt | eq) ? sv[3] : 0.f;
            }
            {
                const int ls1 = ls0 + 1;
                const bool lt = lane < ls1, eq = lane == ls1;
                m[4] = lt ? sv[4] : eq ? v[4].x : 0.f;
                m[5] = lt ? sv[5] : eq ? (v[5].x + v[5].y) : 0.f;
                m[6] = lt ? sv[6] : eq ? ((v[6].x + v[6].y) + v[6].z) : 0.f;
                m[7] = (lt | eq) ? sv[7] : 0.f;
            }
            const float mc = multireduce8(m, lane);
            if (lane < 8) sCutM[lrg + lane] = mc;
        }
        if (antiRole) {
            // cut column lc = 127 - lr; kA = 3-(u&3) (compile-time),
            // lsA = ((127-lrg)>>2) - (u>>2).
            const int lsA0 = (127 - lrg) >> 2;
            float m[8];
            {
                const bool lt = lane < lsA0, eq = lane == lsA0;
                m[0] = (lt | eq) ? sv[0] : 0.f;
                m[1] = lt ? sv[1] : eq ? ((v[1].x + v[1].y) + v[1].z) : 0.f;
                m[2] = lt ? sv[2] : eq ? (v[2].x + v[2].y) : 0.f;
                m[3] = lt ? sv[3] : eq ? v[3].x : 0.f;
            }
            {
                const int lsA1 = lsA0 - 1;
                const bool lt = lane < lsA1, eq = lane == lsA1;
                m[4] = (lt | eq) ? sv[4] : 0.f;
                m[5] = lt ? sv[5] : eq ? ((v[5].x + v[5].y) + v[5].z) : 0.f;
                m[6] = lt ? sv[6] : eq ? (v[6].x + v[6].y) : 0.f;
                m[7] = lt ? sv[7] : eq ? v[7].x : 0.f;
            }
            const float mc = multireduce8(m, lane);
            if (lane < 8) sCutA[lrg + lane] = mc;
        }

        // snapshots (strict col prefixes, read acc BEFORE update) + packed acc update
#pragma unroll
        for (int u = 0; u < 8; u++) {
            const int lr = lrg + u;
            if (mainRole) {
                const int ls = 8 * wr + 2 * g + (u >> 2);
                if (lane == ls) {
                    float lo, hi, sn;
                    if ((u & 3) < 2) { unpack2(acc01, lo, hi); sn = ((u & 3) == 0) ? lo : hi; }
                    else             { unpack2(acc23, lo, hi); sn = ((u & 3) == 2) ? lo : hi; }
                    sSnapM[lr] = sn;
                }
            }
            if (antiRole) {
                const int lsA = ((127 - lrg) >> 2) - (u >> 2);
                const int kA = 3 - (u & 3);   // compile-time
                if (lane == lsA) {
                    const float e = (kA == 0) ? v[u].x : (kA == 1) ? v[u].y
                                  : (kA == 2) ? v[u].z : v[u].w;
                    float lo, hi, sn;
                    if (kA < 2) { unpack2(acc01, lo, hi); sn = (kA == 0) ? lo : hi; }
                    else        { unpack2(acc23, lo, hi); sn = (kA == 2) ? lo : hi; }
                    sSnapA[127 - lr] = sn;
                    sDA[lr] = e;
                }
            }
            acc01 = addf32x2(acc01, pack2(v[u].x, v[u].y));
            acc23 = addf32x2(acc23, pack2(v[u].z, v[u].w));
        }
    }

    {
        float a0, a1, a2, a3;
        unpack2(acc01, a0, a1);
        unpack2(acc23, a2, a3);
        reinterpret_cast<float4*>(&sColPart[wr][c0])[lane] = make_float4(a0, a1, a2, a3);
    }
    __syncthreads();

    // ---- slab combine: columns ----
    {
        const int c = tid;
        const float q0 = sColPart[0][c], q1 = sColPart[1][c],
                    q2 = sColPart[2][c], q3 = sColPart[3][c];
        g_colsum[p][s][c] = (q0 + q1) + (q2 + q3);

        const int band = c >> 7;
        if (band == s) {
            const int lr = c - 128 * s;
            const int rg = lr >> 5;
            float sn = sSnapM[lr];
            if (rg > 0) sn += q0;
            if (rg > 1) sn += q1;
            if (rg > 2) sn += q2;
            g_snapM[p][c] = sn;
        }
        if (band == 3 - s) {
            const int la = c - 128 * (3 - s);   // == 127 - lr
            const int rg = (127 - la) >> 5;
            float sn = sSnapA[la];
            if (rg > 0) sn += q0;
            if (rg > 1) sn += q1;
            if (rg > 2) sn += q2;
            g_snapA[p][c] = sn;
        }
    }
    // ---- slab combine: rows ----
    if (tid < SLAB) {
        const int lr = tid;
        const int gr = 128 * s + lr;
        const float b0 = sBandRow[0][lr], b1 = sBandRow[1][lr],
                    b2 = sBandRow[2][lr], b3 = sBandRow[3][lr];
        g_RT[p][gr] = (b0 + b1) + (b2 + b3);

        float pm = sCutM[lr];
        if (s > 0) pm += b0;
        if (s > 1) pm += b1;
        if (s > 2) pm += b2;
        g_PM[p][gr] = pm;

        const int ab = 3 - s;
        float pa = sCutA[lr];
        if (ab > 0) pa += b0;
        if (ab > 1) pa += b1;
        if (ab > 2) pa += b2;
        g_PA[p][gr] = pa;

        g_DA[p][gr] = sDA[lr];
    }

    // ---- last-block-per-plane fused combine ----
    __threadfence();
    __syncthreads();
    if (tid == 0) {
        const unsigned t = atomicAdd(&g_cnt[p], 1u);
        amLast = (t == 3u);
        if (amLast) g_cnt[p] = 0;
    }
    __syncthreads();
    if (!amLast) return;

    {
        const int i = tid;
        const float q0 = g_colsum[p][0][i], q1 = g_colsum[p][1][i],
                    q2 = g_colsum[p][2][i], q3 = g_colsum[p][3][i];
        cCT[i] = (q0 + q1) + (q2 + q3);

        const int jm = i >> 7;
        float a1 = g_snapM[p][i];
        if (jm > 0) a1 += q0;
        if (jm > 1) a1 += q1;
        if (jm > 2) a1 += q2;
        cA1[i] = a1;

        const int ja = (SZ - 1 - i) >> 7;
        float a2 = g_snapA[p][i];
        if (ja > 0) a2 += q0;
        if (ja > 1) a2 += q1;
        if (ja > 2) a2 += q2;
        cA2[i] = a2;

        cRT[i] = g_RT[p][i]; cPM[i] = g_PM[p][i]; cPA[i] = g_PA[p][i]; cDAo[i] = g_DA[p][i];
    }
    __syncthreads();
    {
        const int i = tid;
        const int m = SZ - 1 - i;

        const float tl = cPM[i] + cA1[i];
        const float tr = cRT[i] - cPA[i] + cDAo[i] + cA2[m];
        const float bl = cPA[m] + cCT[i] - cA2[i] - cDAo[m];
        const float br = cRT[m] - cPM[m] + cCT[m] - cA1[m];

        const float inv = 1.0f / (float)(2 * i + 1);
        const int b  = p >> 3;
        const int ch = p & 7;
        float* __restrict__ o = out + ((size_t)(b * SZ + i)) * 32 + ch;
        o[0]  = tl * inv;
        o[8]  = tr * inv;
        o[16] = bl * inv;
        o[24] = br * inv;
    }
}

extern "C" void kernel_launch(void* const* d_in, const int* in_sizes, int n_in,
                              void* d_out, int out_size) {
    const float* x = (const float*)d_in[0];
    float* out = (float*)d_out;
    const int planes = in_sizes[0] / (SZ * SZ);   // 256
    slab_kernel<<<planes * 4, 512>>>(x, out);
}